// round 12
// baseline (speedup 1.0000x reference)
#include <cuda_runtime.h>
#include <cuda.h>
#include <cstdint>
#include <cstddef>

// ---------------------------------------------------------------------------
// DynamicGraphBuilder: per (b,t) item: 19x19 cosine similarity -> /0.1 ->
// softmax -> top-3 keep -> threshold 1e-4 -> 0.5*(A+A^T).
// One warp per item. F staged via ONE 5-D TMA tensormap (4 UTMALDG per warp,
// 128B-swizzled segments [d_outer][n][128B]) -> no LSU staging wavefronts.
// Gram: 15 upper-tri 4x4 register tiles over STRIDED groups (group a =
// {a, a+5, a+10, a+15}), 2 granule-parity halves (30 lanes), LDS.128 operands
// feeding packed fma.rn.f32x2. Fused-mirror scatter. 5 CTAs/SM.
// ---------------------------------------------------------------------------

namespace {

constexpr int kN = 19;
constexpr int kT = 2048;
constexpr int kD = 128;
constexpr int kItems = 32 * kT;            // 65536
constexpr int kWarpsPerCta = 4;
constexpr int kThreads = kWarpsPerCta * 32;
constexpr int kGrid = kItems / kWarpsPerCta;

constexpr float kInvTemp = 10.0f;          // 1 / 0.1
constexpr float kThresh = 1e-4f;

// Per-warp F: 4 segments (one per 128B d-chunk) x 20 rows x 128B = 10240 B.
// Segment dd holds d in [32*dd, 32*dd+32), rows 0..18 TMA-filled (SW128
// swizzle, key = (n + 4*dd) & 7 from absolute addr bits), row 19 = zero pad.
// G (19 x stride 21 floats) ALIASES F start (F dead before first G write).
constexpr int kSegBytes = 20 * 128;        // 2560
constexpr int kWarpBytes = 4 * kSegBytes;  // 10240
constexpr int kGS = 21;

__device__ __forceinline__ unsigned long long ffma2(unsigned long long a,
                                                    unsigned long long b,
                                                    unsigned long long c) {
    unsigned long long d;
    asm("fma.rn.f32x2 %0, %1, %2, %3;" : "=l"(d) : "l"(a), "l"(b), "l"(c));
    return d;
}

__device__ __forceinline__ float2 unpack2(unsigned long long v) {
    float2 r;
    asm("mov.b64 {%0, %1}, %2;" : "=f"(r.x), "=f"(r.y) : "l"(v));
    return r;
}

__device__ __forceinline__ void lds128(unsigned addr,
                                       unsigned long long& lo,
                                       unsigned long long& hi) {
    asm volatile("ld.shared.v2.u64 {%0, %1}, [%2];"
                 : "=l"(lo), "=l"(hi) : "r"(addr));
}

__device__ __forceinline__ void mbar_wait0(unsigned mb) {
    asm volatile(
        "{\n\t.reg .pred P;\n"
        "LW_%=:\n\t"
        "mbarrier.try_wait.parity.acquire.cta.shared::cta.b64 P, [%0], %1, 0x989680;\n\t"
        "@P bra LD_%=;\n\t"
        "bra LW_%=;\n"
        "LD_%=:\n\t}"
        :: "r"(mb), "r"(0u) : "memory");
}

__global__ void __launch_bounds__(kThreads, 5)
dgb_kernel(const __grid_constant__ CUtensorMap tmap, float* __restrict__ out) {
    __shared__ __align__(1024) float sm[kWarpsPerCta * (kWarpBytes / 4)];
    __shared__ unsigned long long mbars[kWarpsPerCta];

    const int lane = threadIdx.x & 31;
    const int w = threadIdx.x >> 5;
    const int item = blockIdx.x * kWarpsPerCta + w;     // < 65536
    const int b = item >> 11;                           // / kT
    const int t = item & (kT - 1);

    float* __restrict__ Fw = sm + w * (kWarpBytes / 4);
    float* __restrict__ G = Fw;                         // aliases F
    const unsigned fb = (unsigned)__cvta_generic_to_shared(Fw);
    const unsigned mb = (unsigned)__cvta_generic_to_shared(&mbars[w]);

    // ---- TMA: 4 segment loads (d-chunk dd), rows 0..18 each ----
    if (lane == 0) {
        asm volatile("mbarrier.init.shared.b64 [%0], %1;"
                     :: "r"(mb), "r"(1u) : "memory");
    }
    __syncwarp();
    if (lane == 0) {
        asm volatile("mbarrier.arrive.expect_tx.shared.b64 _, [%0], %1;"
                     :: "r"(mb), "r"(4u * 19u * 128u) : "memory");
#pragma unroll
        for (int dd = 0; dd < 4; ++dd) {
            unsigned dst = fb + (unsigned)(dd * kSegBytes);
            asm volatile(
                "cp.async.bulk.tensor.5d.shared::cta.global.tile"
                ".mbarrier::complete_tx::bytes"
                " [%0], [%1, {%2, %3, %4, %5, %6}], [%7];"
                :: "r"(dst), "l"(&tmap),
                   "r"(0), "r"(dd), "r"(t), "r"(0), "r"(b),
                   "r"(mb)
                : "memory");
        }
    }

    // ---- zero pad row 19 of each segment (4 x 128B; 16B per lane) ----
    {
        unsigned z = 0u;
        unsigned dst = fb + (unsigned)((lane >> 3) * kSegBytes + 19 * 128 +
                                       (lane & 7) * 16);
        asm volatile("st.shared.v4.b32 [%0], {%1,%1,%1,%1};"
                     :: "r"(dst), "r"(z) : "memory");
    }
    __syncwarp();
    mbar_wait0(mb);

    // ---- tile map: 15 upper-tri 4x4 tiles; STRIDED groups ----
    // group a = rows {a, a+5, a+10, a+15}  (a = 0..4; row 19 = pad).
    // lane: tile = min(lane>>1, 14), h = lane&1. Lanes 30,31 dup tile 14.
    const int s = lane;
    int tile = s >> 1;
    if (tile > 14) tile = 14;
    const int h = s & 1;
    int a, q;
    if (tile < 5)       { a = 0; q = tile; }
    else if (tile < 9)  { a = 1; q = tile - 4; }
    else if (tile < 12) { a = 2; q = tile - 7; }
    else if (tile < 14) { a = 3; q = tile - 9; }
    else                { a = 4; q = 4; }

    int nA[4], nB[4];
    unsigned rowA[4], rowB[4];
#pragma unroll
    for (int r = 0; r < 4; ++r) {
        nA[r] = a + 5 * r;
        nB[r] = q + 5 * r;
        rowA[r] = fb + (unsigned)(nA[r] * 128);
        rowB[r] = fb + (unsigned)(nB[r] * 128);
    }

    unsigned long long acc[4][4];
#pragma unroll
    for (int r = 0; r < 4; ++r)
#pragma unroll
        for (int c = 0; c < 4; ++c) acc[r][c] = 0ull;

    // Lane covers granules of parity h. Logical granule g = 8*dd + 2*ii + h;
    // physical granule = gc ^ key,  key = (n + 4*dd) & 7 = (n&7) ^ (4*(dd&1)).
    // Per instruction: 5 consecutive rows x 2 parities -> keys distinct,
    // <=2 wavefronts (160B distinct).
#pragma unroll
    for (int dd = 0; dd < 4; ++dd) {
        const unsigned sseg = (unsigned)(dd * kSegBytes);
        const int xk = (dd & 1) << 2;
        unsigned bA[4], bB[4];
#pragma unroll
        for (int r = 0; r < 4; ++r) {
            bA[r] = rowA[r] + sseg +
                    (unsigned)((h ^ (nA[r] & 7) ^ xk) << 4);
            bB[r] = rowB[r] + sseg +
                    (unsigned)((h ^ (nB[r] & 7) ^ xk) << 4);
        }
#pragma unroll
        for (int ii = 0; ii < 4; ++ii) {
            const unsigned cx = (unsigned)(ii << 5);   // (2*ii)<<4, XOR-safe
            unsigned long long alo[4], ahi[4];
#pragma unroll
            for (int r = 0; r < 4; ++r)
                lds128(bA[r] ^ cx, alo[r], ahi[r]);
#pragma unroll
            for (int c = 0; c < 4; ++c) {
                unsigned long long blo, bhi;
                lds128(bB[c] ^ cx, blo, bhi);
#pragma unroll
                for (int r = 0; r < 4; ++r) {
                    acc[r][c] = ffma2(alo[r], blo, acc[r][c]);
                    acc[r][c] = ffma2(ahi[r], bhi, acc[r][c]);
                }
            }
        }
    }
    __syncwarp();   // all gram loads done before G overwrites F

    // ---- reduce halves; fused scatter: h=0 -> (R,C), h=1 -> (C,R) ----
#pragma unroll
    for (int r = 0; r < 4; ++r) {
#pragma unroll
        for (int c = 0; c < 4; ++c) {
            float2 p = unpack2(acc[r][c]);
            float v = p.x + p.y;
            v += __shfl_xor_sync(0xffffffffu, v, 1);
            const int R = nA[r], C = nB[c];
            if (s < 30 && R < kN && C < kN) {
                const int idx = h ? (C * kGS + R) : (R * kGS + C);
                G[idx] = v;
            }
        }
    }
    __syncwarp();

    // ---- epilogue: lane i owns row i (lanes >= 19 clamp -> broadcast) ----
    {
        const int ir = (lane < kN) ? lane : (kN - 1);
        float g[kN];
#pragma unroll
        for (int j = 0; j < kN; ++j) g[j] = G[ir * kGS + j];

        const float rinv = rsqrtf(fmaxf(g[ir], 1e-24f));
        const float ri10 = rinv * kInvTemp;

        float m = -1e30f;
#pragma unroll
        for (int j = 0; j < kN; ++j) {
            float rj = __shfl_sync(0xffffffffu, rinv, j);
            g[j] = g[j] * ri10 * rj;
            m = fmaxf(m, g[j]);
        }
        float sum = 0.f;
#pragma unroll
        for (int j = 0; j < kN; ++j) {
            g[j] = __expf(g[j] - m);
            sum += g[j];
        }
        const float inv = 1.0f / sum;

        float t1 = -1e30f, t2 = -1e30f, t3 = -1e30f;
#pragma unroll
        for (int j = 0; j < kN; ++j) {
            float v = g[j] * inv;
            g[j] = v;
            if (v > t1)      { t3 = t2; t2 = t1; t1 = v; }
            else if (v > t2) { t3 = t2; t2 = v; }
            else if (v > t3) { t3 = v; }
        }

        __syncwarp();   // row reads complete before sparse overwrite
        if (lane < kN) {
#pragma unroll
            for (int j = 0; j < kN; ++j) {
                float v = g[j];
                G[lane * kGS + j] = (v >= t3 && v > kThresh) ? v : 0.0f;
            }
        }
    }
    __syncwarp();

    // ---- symmetrize + coalesced store: 361 floats per item ----
    {
        float* dst = out + (size_t)item * (kN * kN);
#pragma unroll
        for (int k = lane; k < kN * kN; k += 32) {
            int ii = k / kN;
            int jj = k - ii * kN;
            dst[k] = 0.5f * (G[ii * kGS + jj] + G[jj * kGS + ii]);
        }
    }
}

}  // namespace

extern "C" void kernel_launch(void* const* d_in, const int* in_sizes, int n_in,
                              void* d_out, int out_size) {
    (void)in_sizes; (void)n_in; (void)out_size;
    const float* feat = (const float*)d_in[0];
    float* out = (float*)d_out;

    // Encode the 5-D tensormap host-side each call (stateless, no -lcuda:
    // fetch the driver entry point through the runtime).
    typedef CUresult (*EncodeFn)(
        CUtensorMap*, CUtensorMapDataType, cuuint32_t, void*,
        const cuuint64_t*, const cuuint64_t*, const cuuint32_t*,
        const cuuint32_t*, CUtensorMapInterleave, CUtensorMapSwizzle,
        CUtensorMapL2promotion, CUtensorMapFloatOOBfill);
    void* sym = nullptr;
    cudaDriverEntryPointQueryResult qres;
    cudaGetDriverEntryPoint("cuTensorMapEncodeTiled", &sym,
                            cudaEnableDefault, &qres);
    CUtensorMap tmap;
    if (sym) {
        // dims (elems): d_inner=32, d_outer=4, t=2048, n=19, b=32
        cuuint64_t dims[5]    = {32, 4, 2048, 19, 32};
        cuuint64_t strides[4] = {128, 512, 1048576, 19922944};  // bytes
        cuuint32_t box[5]     = {32, 1, 1, 19, 1};
        cuuint32_t estr[5]    = {1, 1, 1, 1, 1};
        ((EncodeFn)sym)(&tmap, CU_TENSOR_MAP_DATA_TYPE_FLOAT32, 5,
                        (void*)feat, dims, strides, box, estr,
                        CU_TENSOR_MAP_INTERLEAVE_NONE,
                        CU_TENSOR_MAP_SWIZZLE_128B,
                        CU_TENSOR_MAP_L2_PROMOTION_L2_128B,
                        CU_TENSOR_MAP_FLOAT_OOB_FILL_NONE);
    }
    dgb_kernel<<<kGrid, kThreads>>>(tmap, out);
}

// round 13
// speedup vs baseline: 1.2861x; 1.2861x over previous
#include <cuda_runtime.h>
#include <cstdint>
#include <cstddef>

// ---------------------------------------------------------------------------
// DynamicGraphBuilder: per (b,t) item: 19x19 cosine similarity -> /0.1 ->
// softmax -> top-3 keep -> threshold 1e-4 -> 0.5*(A+A^T).
// One warp per item. F staged in SMEM with a group-level XOR granule swizzle
// (key=(5*grp)&7, groups of 4 consecutive rows); Gram via 15 upper-tri 4x4
// register tiles, d split by granule parity (30 lanes), LDS.128 operands
// feeding packed fma.rn.f32x2 (128 gram LDS/item = minimal over tilings).
// Fused-mirror scatter (16 STS). G aliases F (F dead after gram loop).
// 5 CTAs/SM.
// ---------------------------------------------------------------------------

namespace {

constexpr int kN = 19;
constexpr int kT = 2048;
constexpr int kD = 128;
constexpr int kItems = 32 * kT;            // 65536
constexpr int kWarpsPerCta = 4;
constexpr int kThreads = kWarpsPerCta * 32;
constexpr int kGrid = kItems / kWarpsPerCta;

constexpr float kInvTemp = 10.0f;          // 1 / 0.1
constexpr float kThresh = 1e-4f;

// Per-warp SMEM: F = 19 rows x 128 floats, granule(16B)-swizzled with
// key(n) = (5*(n>>2)) & 7 (shared by the 4 rows of a group).
// G (19 x stride 21 = 399 words) ALIASES the start of F: F is dead before
// the first G write (scatter happens after the full gram loop + syncwarp).
constexpr int kGS = 21;
constexpr int kWarpWords = 19 * 128;       // 2432 words = 9728 B / warp
// 4 warps -> 38912 B static shared -> 5 CTAs / SM

__device__ __forceinline__ int gkey(int grp) { return (5 * grp) & 7; }

__device__ __forceinline__ unsigned long long ffma2(unsigned long long a,
                                                    unsigned long long b,
                                                    unsigned long long c) {
    unsigned long long d;
    asm("fma.rn.f32x2 %0, %1, %2, %3;" : "=l"(d) : "l"(a), "l"(b), "l"(c));
    return d;
}

__device__ __forceinline__ float2 unpack2(unsigned long long v) {
    float2 r;
    asm("mov.b64 {%0, %1}, %2;" : "=f"(r.x), "=f"(r.y) : "l"(v));
    return r;
}

__device__ __forceinline__ void lds128(unsigned addr,
                                       unsigned long long& lo,
                                       unsigned long long& hi) {
    asm volatile("ld.shared.v2.u64 {%0, %1}, [%2];"
                 : "=l"(lo), "=l"(hi) : "r"(addr));
}

__global__ void __launch_bounds__(kThreads, 5)
dgb_kernel(const float* __restrict__ feat, float* __restrict__ out) {
    __shared__ float sm[kWarpsPerCta * kWarpWords];

    const int lane = threadIdx.x & 31;
    const int w = threadIdx.x >> 5;
    const int item = blockIdx.x * kWarpsPerCta + w;     // < 65536
    const int b = item >> 11;                           // / kT
    const int t = item & (kT - 1);

    float* __restrict__ Fw = sm + w * kWarpWords;
    float* __restrict__ G = Fw;                         // aliases F (see above)
    const unsigned fb = (unsigned)__cvta_generic_to_shared(Fw);

    // ---- stage 19 rows GMEM -> SMEM (cp.async 16B, granule swizzle) ----
    {
        const float* src0 =
            feat + (((size_t)b * kN) * kT + (size_t)t) * kD + lane * 4;
#pragma unroll
        for (int n = 0; n < kN; ++n) {
            unsigned dst = fb + (unsigned)(n * 512 + ((lane ^ gkey(n >> 2)) << 4));
            const float* src = src0 + (size_t)n * (kT * kD);
            asm volatile("cp.async.cg.shared.global [%0], [%1], 16;"
                         :: "r"(dst), "l"(src) : "memory");
        }
        asm volatile("cp.async.commit_group;" ::: "memory");
        asm volatile("cp.async.wait_group 0;" ::: "memory");
    }
    __syncwarp();

    // ---- tile map: 15 upper-tri 4x4 tiles over a padded 20x20 grid ----
    // lane s: tile = min(s>>1, 14), h = s&1 (granule parity). Lanes 30,31
    // duplicate tile 14.
    const int s = lane;
    int tile = s >> 1;
    if (tile > 14) tile = 14;
    const int h = s & 1;
    int a, q;
    if (tile < 5)       { a = 0; q = tile; }
    else if (tile < 9)  { a = 1; q = tile - 4; }
    else if (tile < 12) { a = 2; q = tile - 7; }
    else if (tile < 14) { a = 3; q = tile - 9; }
    else                { a = 4; q = 4; }

    const int fa = gkey(a);
    const int fq = gkey(q);

    // Row base addresses (bytes, shared space); rows >= 19 clamp to 18
    // (their products are predicated out of the gram scatter).
    unsigned baseA[4], baseB[4];
#pragma unroll
    for (int r = 0; r < 4; ++r) {
        int rn = 4 * a + r; if (rn > 18) rn = 18;
        int cn = 4 * q + r; if (cn > 18) cn = 18;
        baseA[r] = fb + (unsigned)(rn * 512);
        baseB[r] = fb + (unsigned)(cn * 512);
    }

    unsigned long long acc[4][4];
#pragma unroll
    for (int r = 0; r < 4; ++r)
#pragma unroll
        for (int c = 0; c < 4; ++c) acc[r][c] = 0ull;

    // Lane covers granules g = 2*it + h  (16 granules x 4 floats = 64 d).
#pragma unroll
    for (int it = 0; it < 16; ++it) {
        const int g = 2 * it + h;
        const unsigned offA = (unsigned)((g ^ fa) << 4);
        const unsigned offB = (unsigned)((g ^ fq) << 4);
        unsigned long long alo[4], ahi[4];
#pragma unroll
        for (int r = 0; r < 4; ++r)
            lds128(baseA[r] + offA, alo[r], ahi[r]);
#pragma unroll
        for (int c = 0; c < 4; ++c) {
            unsigned long long blo, bhi;
            lds128(baseB[c] + offB, blo, bhi);
#pragma unroll
            for (int r = 0; r < 4; ++r) {
                acc[r][c] = ffma2(alo[r], blo, acc[r][c]);
                acc[r][c] = ffma2(ahi[r], bhi, acc[r][c]);
            }
        }
    }
    __syncwarp();   // all gram loads done in all lanes before G overwrites F

    // ---- reduce halves; fused scatter: h=0 -> (R,C), h=1 -> (C,R) ----
#pragma unroll
    for (int r = 0; r < 4; ++r) {
#pragma unroll
        for (int c = 0; c < 4; ++c) {
            float2 p = unpack2(acc[r][c]);
            float v = p.x + p.y;
            v += __shfl_xor_sync(0xffffffffu, v, 1);
            const int R = 4 * a + r, C = 4 * q + c;
            if (s < 30 && R < kN && C < kN) {
                const int idx = h ? (C * kGS + R) : (R * kGS + C);
                G[idx] = v;
            }
        }
    }
    __syncwarp();

    // ---- epilogue: lane i owns row i (lanes >= 19 clamp -> broadcast) ----
    {
        const int ir = (lane < kN) ? lane : (kN - 1);
        float g[kN];
#pragma unroll
        for (int j = 0; j < kN; ++j) g[j] = G[ir * kGS + j];

        const float rinv = rsqrtf(fmaxf(g[ir], 1e-24f));
        const float ri10 = rinv * kInvTemp;

        float m = -1e30f;
#pragma unroll
        for (int j = 0; j < kN; ++j) {
            float rj = __shfl_sync(0xffffffffu, rinv, j);
            g[j] = g[j] * ri10 * rj;
            m = fmaxf(m, g[j]);
        }
        float sum = 0.f;
#pragma unroll
        for (int j = 0; j < kN; ++j) {
            g[j] = __expf(g[j] - m);
            sum += g[j];
        }
        const float inv = 1.0f / sum;

        float t1 = -1e30f, t2 = -1e30f, t3 = -1e30f;
#pragma unroll
        for (int j = 0; j < kN; ++j) {
            float v = g[j] * inv;
            g[j] = v;
            if (v > t1)      { t3 = t2; t2 = t1; t1 = v; }
            else if (v > t2) { t3 = t2; t2 = v; }
            else if (v > t3) { t3 = v; }
        }

        __syncwarp();   // row reads complete before sparse overwrite
        if (lane < kN) {
#pragma unroll
            for (int j = 0; j < kN; ++j) {
                float v = g[j];
                G[lane * kGS + j] = (v >= t3 && v > kThresh) ? v : 0.0f;
            }
        }
    }
    __syncwarp();

    // ---- symmetrize + coalesced store: 361 floats per item ----
    {
        float* dst = out + (size_t)item * (kN * kN);
#pragma unroll
        for (int k = lane; k < kN * kN; k += 32) {
            int ii = k / kN;
            int jj = k - ii * kN;
            dst[k] = 0.5f * (G[ii * kGS + jj] + G[jj * kGS + ii]);
        }
    }
}

}  // namespace

extern "C" void kernel_launch(void* const* d_in, const int* in_sizes, int n_in,
                              void* d_out, int out_size) {
    (void)in_sizes; (void)n_in; (void)out_size;
    const float* feat = (const float*)d_in[0];
    float* out = (float*)d_out;
    dgb_kernel<<<kGrid, kThreads>>>(feat, out);
}

// round 15
// speedup vs baseline: 1.3023x; 1.0126x over previous
#include <cuda_runtime.h>
#include <cstdint>
#include <cstddef>

// ---------------------------------------------------------------------------
// DynamicGraphBuilder: per (b,t) item: 19x19 cosine similarity -> /0.1 ->
// softmax -> top-3 keep -> threshold 1e-4 -> 0.5*(A+A^T).
// One warp per item. F staged in SMEM with a group-level XOR granule swizzle
// (key=(5*grp)&7, groups of 4 consecutive rows); Gram via 15 upper-tri 4x4
// register tiles, d split by granule parity (30 lanes), LDS.128 operands
// feeding packed fma.rn.f32x2 (128 gram LDS/item = minimal over tilings).
// Fused-mirror scatter (16 STS). G aliases F (F dead after gram loop),
// stride 20 words -> 16B-aligned rows -> vectorized epilogue (LDS.128/STS.128).
// 5 CTAs/SM.
// ---------------------------------------------------------------------------

namespace {

constexpr int kN = 19;
constexpr int kT = 2048;
constexpr int kD = 128;
constexpr int kItems = 32 * kT;            // 65536
constexpr int kWarpsPerCta = 4;
constexpr int kThreads = kWarpsPerCta * 32;
constexpr int kGrid = kItems / kWarpsPerCta;

constexpr float kInvTemp = 10.0f;          // 1 / 0.1
constexpr float kThresh = 1e-4f;

// Per-warp SMEM: F = 19 rows x 128 floats, granule(16B)-swizzled with
// key(n) = (5*(n>>2)) & 7 (shared by the 4 rows of a group).
// G (19 rows x stride 20, 16B-aligned; word 19 of each row = pad) ALIASES
// the start of F: F is dead before the first G write.
constexpr int kGS = 20;
constexpr int kWarpWords = 19 * 128;       // 2432 words = 9728 B / warp
// 4 warps -> 38912 B static shared -> 5 CTAs / SM

__device__ __forceinline__ int gkey(int grp) { return (5 * grp) & 7; }

__device__ __forceinline__ unsigned long long ffma2(unsigned long long a,
                                                    unsigned long long b,
                                                    unsigned long long c) {
    unsigned long long d;
    asm("fma.rn.f32x2 %0, %1, %2, %3;" : "=l"(d) : "l"(a), "l"(b), "l"(c));
    return d;
}

__device__ __forceinline__ float2 unpack2(unsigned long long v) {
    float2 r;
    asm("mov.b64 {%0, %1}, %2;" : "=f"(r.x), "=f"(r.y) : "l"(v));
    return r;
}

__device__ __forceinline__ void lds128(unsigned addr,
                                       unsigned long long& lo,
                                       unsigned long long& hi) {
    asm volatile("ld.shared.v2.u64 {%0, %1}, [%2];"
                 : "=l"(lo), "=l"(hi) : "r"(addr));
}

__global__ void __launch_bounds__(kThreads, 5)
dgb_kernel(const float* __restrict__ feat, float* __restrict__ out) {
    __shared__ float sm[kWarpsPerCta * kWarpWords];

    const int lane = threadIdx.x & 31;
    const int w = threadIdx.x >> 5;
    const int item = blockIdx.x * kWarpsPerCta + w;     // < 65536
    const int b = item >> 11;                           // / kT
    const int t = item & (kT - 1);

    float* __restrict__ Fw = sm + w * kWarpWords;
    float* __restrict__ G = Fw;                         // aliases F (see above)
    const unsigned fb = (unsigned)__cvta_generic_to_shared(Fw);

    // ---- stage 19 rows GMEM -> SMEM (cp.async 16B, granule swizzle) ----
    {
        const float* src0 =
            feat + (((size_t)b * kN) * kT + (size_t)t) * kD + lane * 4;
#pragma unroll
        for (int n = 0; n < kN; ++n) {
            unsigned dst = fb + (unsigned)(n * 512 + ((lane ^ gkey(n >> 2)) << 4));
            const float* src = src0 + (size_t)n * (kT * kD);
            asm volatile("cp.async.cg.shared.global [%0], [%1], 16;"
                         :: "r"(dst), "l"(src) : "memory");
        }
        asm volatile("cp.async.commit_group;" ::: "memory");
        asm volatile("cp.async.wait_group 0;" ::: "memory");
    }
    __syncwarp();

    // ---- tile map: 15 upper-tri 4x4 tiles over a padded 20x20 grid ----
    // lane s: tile = min(s>>1, 14), h = s&1 (granule parity). Lanes 30,31
    // duplicate tile 14.
    const int s = lane;
    int tile = s >> 1;
    if (tile > 14) tile = 14;
    const int h = s & 1;
    int a, q;
    if (tile < 5)       { a = 0; q = tile; }
    else if (tile < 9)  { a = 1; q = tile - 4; }
    else if (tile < 12) { a = 2; q = tile - 7; }
    else if (tile < 14) { a = 3; q = tile - 9; }
    else                { a = 4; q = 4; }

    const int fa = gkey(a);
    const int fq = gkey(q);

    // Row base addresses (bytes, shared space); rows >= 19 clamp to 18
    // (their products are predicated out of the gram scatter).
    unsigned baseA[4], baseB[4];
#pragma unroll
    for (int r = 0; r < 4; ++r) {
        int rn = 4 * a + r; if (rn > 18) rn = 18;
        int cn = 4 * q + r; if (cn > 18) cn = 18;
        baseA[r] = fb + (unsigned)(rn * 512);
        baseB[r] = fb + (unsigned)(cn * 512);
    }

    unsigned long long acc[4][4];
#pragma unroll
    for (int r = 0; r < 4; ++r)
#pragma unroll
        for (int c = 0; c < 4; ++c) acc[r][c] = 0ull;

    // Lane covers granules g = 2*it + h  (16 granules x 4 floats = 64 d).
#pragma unroll
    for (int it = 0; it < 16; ++it) {
        const int g = 2 * it + h;
        const unsigned offA = (unsigned)((g ^ fa) << 4);
        const unsigned offB = (unsigned)((g ^ fq) << 4);
        unsigned long long alo[4], ahi[4];
#pragma unroll
        for (int r = 0; r < 4; ++r)
            lds128(baseA[r] + offA, alo[r], ahi[r]);
#pragma unroll
        for (int c = 0; c < 4; ++c) {
            unsigned long long blo, bhi;
            lds128(baseB[c] + offB, blo, bhi);
#pragma unroll
            for (int r = 0; r < 4; ++r) {
                acc[r][c] = ffma2(alo[r], blo, acc[r][c]);
                acc[r][c] = ffma2(ahi[r], bhi, acc[r][c]);
            }
        }
    }
    __syncwarp();   // all gram loads done in all lanes before G overwrites F

    // ---- reduce halves; fused scatter: h=0 -> (R,C), h=1 -> (C,R) ----
#pragma unroll
    for (int r = 0; r < 4; ++r) {
#pragma unroll
        for (int c = 0; c < 4; ++c) {
            float2 p = unpack2(acc[r][c]);
            float v = p.x + p.y;
            v += __shfl_xor_sync(0xffffffffu, v, 1);
            const int R = 4 * a + r, C = 4 * q + c;
            if (s < 30 && R < kN && C < kN) {
                const int idx = h ? (C * kGS + R) : (R * kGS + C);
                G[idx] = v;
            }
        }
    }
    __syncwarp();

    // ---- epilogue: lane i owns row i (lanes >= 19 clamp -> broadcast) ----
    {
        const int ir = (lane < kN) ? lane : (kN - 1);

        // Vectorized row load: 5 x LDS.128 (20 words; word 19 = pad, unused).
        float g[20];
        {
            const float4* rowp = reinterpret_cast<const float4*>(&G[ir * kGS]);
#pragma unroll
            for (int v = 0; v < 5; ++v) {
                float4 x = rowp[v];
                g[4 * v + 0] = x.x; g[4 * v + 1] = x.y;
                g[4 * v + 2] = x.z; g[4 * v + 3] = x.w;
            }
        }

        const float rinv = rsqrtf(fmaxf(g[ir], 1e-24f));
        const float ri10 = rinv * kInvTemp;

        float m = -1e30f;
#pragma unroll
        for (int j = 0; j < kN; ++j) {
            float rj = __shfl_sync(0xffffffffu, rinv, j);
            g[j] = g[j] * ri10 * rj;
            m = fmaxf(m, g[j]);
        }
        float sum = 0.f;
#pragma unroll
        for (int j = 0; j < kN; ++j) {
            g[j] = __expf(g[j] - m);
            sum += g[j];
        }
        const float inv = 1.0f / sum;

        float t1 = -1e30f, t2 = -1e30f, t3 = -1e30f;
#pragma unroll
        for (int j = 0; j < kN; ++j) {
            float v = g[j] * inv;
            g[j] = v;
            if (v > t1)      { t3 = t2; t2 = t1; t1 = v; }
            else if (v > t2) { t3 = t2; t2 = v; }
            else if (v > t3) { t3 = v; }
        }

        // sparsify into registers (pad word = 0), then 5 x STS.128
        float kept[20];
#pragma unroll
        for (int j = 0; j < kN; ++j) {
            float v = g[j];
            kept[j] = (v >= t3 && v > kThresh) ? v : 0.0f;
        }
        kept[19] = 0.0f;

        __syncwarp();   // row reads complete before sparse overwrite
        if (lane < kN) {
            float4* rowp = reinterpret_cast<float4*>(&G[lane * kGS]);
#pragma unroll
            for (int v = 0; v < 5; ++v)
                rowp[v] = make_float4(kept[4 * v + 0], kept[4 * v + 1],
                                      kept[4 * v + 2], kept[4 * v + 3]);
        }
    }
    __syncwarp();

    // ---- symmetrize + coalesced store: 361 floats per item ----
    {
        float* dst = out + (size_t)item * (kN * kN);
#pragma unroll
        for (int k = lane; k < kN * kN; k += 32) {
            int ii = k / kN;
            int jj = k - ii * kN;
            dst[k] = 0.5f * (G[ii * kGS + jj] + G[jj * kGS + ii]);
        }
    }
}

}  // namespace

extern "C" void kernel_launch(void* const* d_in, const int* in_sizes, int n_in,
                              void* d_out, int out_size) {
    (void)in_sizes; (void)n_in; (void)out_size;
    const float* feat = (const float*)d_in[0];
    float* out = (float*)d_out;
    dgb_kernel<<<kGrid, kThreads>>>(feat, out);
}

// round 17
// speedup vs baseline: 1.3046x; 1.0018x over previous
#include <cuda_runtime.h>
#include <cstdint>
#include <cstddef>

// ---------------------------------------------------------------------------
// DynamicGraphBuilder: per (b,t) item: 19x19 cosine similarity -> /0.1 ->
// softmax -> top-3 keep -> threshold 1e-4 -> 0.5*(A+A^T).
// One warp per item. F staged in SMEM with a group-level XOR granule swizzle
// (key=(5*grp)&7); Gram via 15 upper-tri 4x4 register tiles, d split by
// granule parity (30 lanes), LDS.128 operands feeding packed fma.rn.f32x2.
// Fused-mirror scatter. Epilogue: transpose via conflict-free column scatter
// (19 STS.32) + vectorized row read-back; output through a block-contiguous
// staging buffer and 128-bit STG (4-item block = 5776 B, 16B-aligned).
// 5 CTAs/SM.
// ---------------------------------------------------------------------------

namespace {

constexpr int kN = 19;
constexpr int kT = 2048;
constexpr int kD = 128;
constexpr int kItems = 32 * kT;            // 65536
constexpr int kWarpsPerCta = 4;
constexpr int kThreads = kWarpsPerCta * 32;
constexpr int kGrid = kItems / kWarpsPerCta;

constexpr float kInvTemp = 10.0f;          // 1 / 0.1
constexpr float kThresh = 1e-4f;

// Per-warp SMEM: F = 19 rows x 128 floats, granule(16B)-swizzled with
// key(n) = (5*(n>>2)) & 7. G (19 rows x stride 20, 16B-aligned; word 19 of
// each row = pad) ALIASES the start of F (F dead before first G write).
// After the row loads, the same region is reused as Tr (sparse transpose).
constexpr int kGS = 20;
constexpr int kWarpWords = 19 * 128;       // 2432 words = 9728 B / warp
// Block staging: yblk[4*361] floats = 5776 B. Total 44688 B -> 5 CTAs / SM.

__device__ __forceinline__ int gkey(int grp) { return (5 * grp) & 7; }

__device__ __forceinline__ unsigned long long ffma2(unsigned long long a,
                                                    unsigned long long b,
                                                    unsigned long long c) {
    unsigned long long d;
    asm("fma.rn.f32x2 %0, %1, %2, %3;" : "=l"(d) : "l"(a), "l"(b), "l"(c));
    return d;
}

__device__ __forceinline__ float2 unpack2(unsigned long long v) {
    float2 r;
    asm("mov.b64 {%0, %1}, %2;" : "=f"(r.x), "=f"(r.y) : "l"(v));
    return r;
}

__device__ __forceinline__ void lds128(unsigned addr,
                                       unsigned long long& lo,
                                       unsigned long long& hi) {
    asm volatile("ld.shared.v2.u64 {%0, %1}, [%2];"
                 : "=l"(lo), "=l"(hi) : "r"(addr));
}

__global__ void __launch_bounds__(kThreads, 5)
dgb_kernel(const float* __restrict__ feat, float* __restrict__ out) {
    __shared__ float sm[kWarpsPerCta * kWarpWords];
    __shared__ float yblk[kWarpsPerCta * kN * kN];     // 1444 floats

    const int lane = threadIdx.x & 31;
    const int w = threadIdx.x >> 5;
    const int item = blockIdx.x * kWarpsPerCta + w;     // < 65536
    const int b = item >> 11;                           // / kT
    const int t = item & (kT - 1);

    float* __restrict__ Fw = sm + w * kWarpWords;
    float* __restrict__ G = Fw;                         // aliases F
    const unsigned fb = (unsigned)__cvta_generic_to_shared(Fw);

    // ---- stage 19 rows GMEM -> SMEM (cp.async 16B, granule swizzle) ----
    {
        const float* src0 =
            feat + (((size_t)b * kN) * kT + (size_t)t) * kD + lane * 4;
#pragma unroll
        for (int n = 0; n < kN; ++n) {
            unsigned dst = fb + (unsigned)(n * 512 + ((lane ^ gkey(n >> 2)) << 4));
            const float* src = src0 + (size_t)n * (kT * kD);
            asm volatile("cp.async.cg.shared.global [%0], [%1], 16;"
                         :: "r"(dst), "l"(src) : "memory");
        }
        asm volatile("cp.async.commit_group;" ::: "memory");
        asm volatile("cp.async.wait_group 0;" ::: "memory");
    }
    __syncwarp();

    // ---- tile map: 15 upper-tri 4x4 tiles over a padded 20x20 grid ----
    const int s = lane;
    int tile = s >> 1;
    if (tile > 14) tile = 14;
    const int h = s & 1;
    int a, q;
    if (tile < 5)       { a = 0; q = tile; }
    else if (tile < 9)  { a = 1; q = tile - 4; }
    else if (tile < 12) { a = 2; q = tile - 7; }
    else if (tile < 14) { a = 3; q = tile - 9; }
    else                { a = 4; q = 4; }

    const int fa = gkey(a);
    const int fq = gkey(q);

    unsigned baseA[4], baseB[4];
#pragma unroll
    for (int r = 0; r < 4; ++r) {
        int rn = 4 * a + r; if (rn > 18) rn = 18;
        int cn = 4 * q + r; if (cn > 18) cn = 18;
        baseA[r] = fb + (unsigned)(rn * 512);
        baseB[r] = fb + (unsigned)(cn * 512);
    }

    unsigned long long acc[4][4];
#pragma unroll
    for (int r = 0; r < 4; ++r)
#pragma unroll
        for (int c = 0; c < 4; ++c) acc[r][c] = 0ull;

    // Lane covers granules g = 2*it + h  (16 granules x 4 floats = 64 d).
#pragma unroll
    for (int it = 0; it < 16; ++it) {
        const int g = 2 * it + h;
        const unsigned offA = (unsigned)((g ^ fa) << 4);
        const unsigned offB = (unsigned)((g ^ fq) << 4);
        unsigned long long alo[4], ahi[4];
#pragma unroll
        for (int r = 0; r < 4; ++r)
            lds128(baseA[r] + offA, alo[r], ahi[r]);
#pragma unroll
        for (int c = 0; c < 4; ++c) {
            unsigned long long blo, bhi;
            lds128(baseB[c] + offB, blo, bhi);
#pragma unroll
            for (int r = 0; r < 4; ++r) {
                acc[r][c] = ffma2(alo[r], blo, acc[r][c]);
                acc[r][c] = ffma2(ahi[r], bhi, acc[r][c]);
            }
        }
    }
    __syncwarp();   // all gram loads done in all lanes before G overwrites F

    // ---- reduce halves; fused scatter: h=0 -> (R,C), h=1 -> (C,R) ----
#pragma unroll
    for (int r = 0; r < 4; ++r) {
#pragma unroll
        for (int c = 0; c < 4; ++c) {
            float2 p = unpack2(acc[r][c]);
            float v = p.x + p.y;
            v += __shfl_xor_sync(0xffffffffu, v, 1);
            const int R = 4 * a + r, C = 4 * q + c;
            if (s < 30 && R < kN && C < kN) {
                const int idx = h ? (C * kGS + R) : (R * kGS + C);
                G[idx] = v;
            }
        }
    }
    __syncwarp();

    // ---- epilogue: lane i owns row i (lanes >= 19 clamp -> broadcast) ----
    {
        const int ir = (lane < kN) ? lane : (kN - 1);

        // Vectorized row load: 5 x LDS.128 (word 19 = pad, unused).
        float g[20];
        {
            const float4* rowp = reinterpret_cast<const float4*>(&G[ir * kGS]);
#pragma unroll
            for (int v = 0; v < 5; ++v) {
                float4 x = rowp[v];
                g[4 * v + 0] = x.x; g[4 * v + 1] = x.y;
                g[4 * v + 2] = x.z; g[4 * v + 3] = x.w;
            }
        }

        const float rinv = rsqrtf(fmaxf(g[ir], 1e-24f));
        const float ri10 = rinv * kInvTemp;

        float m = -1e30f;
#pragma unroll
        for (int j = 0; j < kN; ++j) {
            float rj = __shfl_sync(0xffffffffu, rinv, j);
            g[j] = g[j] * ri10 * rj;
            m = fmaxf(m, g[j]);
        }
        float sum = 0.f;
#pragma unroll
        for (int j = 0; j < kN; ++j) {
            g[j] = __expf(g[j] - m);
            sum += g[j];
        }
        const float inv = 1.0f / sum;

        float t1 = -1e30f, t2 = -1e30f, t3 = -1e30f;
#pragma unroll
        for (int j = 0; j < kN; ++j) {
            float v = g[j] * inv;
            g[j] = v;
            if (v > t1)      { t3 = t2; t2 = t1; t1 = v; }
            else if (v > t2) { t3 = t2; t2 = v; }
            else if (v > t3) { t3 = v; }
        }

        // sparsify in regs
        float kept[kN];
#pragma unroll
        for (int j = 0; j < kN; ++j) {
            float v = g[j];
            kept[j] = (v >= t3 && v > kThresh) ? v : 0.0f;
        }

        __syncwarp();   // all row reads done before Tr scatter overwrites G

        // transpose scatter: Tr[j][lane] = kept[j] (conflict-free per j)
        if (lane < kN) {
#pragma unroll
            for (int j = 0; j < kN; ++j)
                G[j * kGS + lane] = kept[j];
        }
        __syncwarp();

        // read own Tr row (= column 'lane' of S) vectorized
        float tr[20];
        {
            const float4* rowp = reinterpret_cast<const float4*>(&G[ir * kGS]);
#pragma unroll
            for (int v = 0; v < 5; ++v) {
                float4 x = rowp[v];
                tr[4 * v + 0] = x.x; tr[4 * v + 1] = x.y;
                tr[4 * v + 2] = x.z; tr[4 * v + 3] = x.w;
            }
        }

        // symmetrize into the block staging buffer (conflict-free stride 19)
        if (lane < kN) {
            float* yb = yblk + (w * kN + lane) * kN;
#pragma unroll
            for (int j = 0; j < kN; ++j)
                yb[j] = 0.5f * (kept[j] + tr[j]);
        }
    }
    __syncthreads();

    // ---- block copy: 4 items = 1444 floats = 361 float4 (16B-aligned) ----
    {
        const float4* src = reinterpret_cast<const float4*>(yblk);
        float4* dst = reinterpret_cast<float4*>(
            out + (size_t)blockIdx.x * (kWarpsPerCta * kN * kN));
#pragma unroll
        for (int f = threadIdx.x; f < (kWarpsPerCta * kN * kN) / 4;
             f += kThreads)
            dst[f] = src[f];
    }
}

}  // namespace

extern "C" void kernel_launch(void* const* d_in, const int* in_sizes, int n_in,
                              void* d_out, int out_size) {
    (void)in_sizes; (void)n_in; (void)out_size;
    const float* feat = (const float*)d_in[0];
    float* out = (float*)d_out;
    dgb_kernel<<<kGrid, kThreads>>>(feat, out);
}